// round 1
// baseline (speedup 1.0000x reference)
#include <cuda_runtime.h>
#include <cstdint>

// Problem constants
#define B_SZ 8
#define T_SEQ 2048
#define D_MODEL 768
#define D_STATE 16
#define D_CONV 4
#define M_ROWS (B_SZ * T_SEQ)          // 16384
#define NCH 16                          // scan chunks
#define TCH (T_SEQ / NCH)               // 128 steps per chunk

// ---------------- scratch (__device__ globals; no runtime alloc) -------------
__device__ float g_xssm [M_ROWS * D_MODEL];
__device__ float g_xconv[M_ROWS * D_MODEL];
__device__ float g_dt   [M_ROWS * D_MODEL];
__device__ float g_Bm   [M_ROWS * D_STATE];
__device__ float g_Cm   [M_ROWS * D_STATE];
__device__ float g_hend [B_SZ * NCH * D_STATE * D_MODEL];
__device__ float g_Pp   [B_SZ * NCH * D_STATE * D_MODEL];
__device__ float g_sin  [B_SZ * NCH * D_STATE * D_MODEL];

// ---------------- GEMM: C[M,N] = A[M,K] * W[N,K]^T (+bias, act) --------------
// act: 0 = none, 1 = softplus(v + bias)
#define BM 128
#define BN 128
#define BK 16

__global__ __launch_bounds__(256)
void gemm_tn_kernel(const float* __restrict__ A, const float* __restrict__ W,
                    const float* __restrict__ bias, float* __restrict__ C,
                    int M, int N, int K, int act)
{
    __shared__ float As[BK][BM];
    __shared__ float Bs[BK][BN];

    const int tid = threadIdx.x;
    const int bm  = blockIdx.y * BM;
    const int bn  = blockIdx.x * BN;
    const int tx  = tid & 15;       // 0..15
    const int ty  = tid >> 4;       // 0..15

    float acc[8][8];
    #pragma unroll
    for (int i = 0; i < 8; i++)
        #pragma unroll
        for (int j = 0; j < 8; j++) acc[i][j] = 0.f;

    for (int k0 = 0; k0 < K; k0 += BK) {
        // cooperative load: 128 rows x 16 cols each tile, as float4
        #pragma unroll
        for (int it = 0; it < 2; it++) {
            int idx = tid + it * 256;        // 0..511
            int row = idx >> 2;              // 0..127
            int cg  = (idx & 3) << 2;        // 0,4,8,12
            float4 a = *reinterpret_cast<const float4*>(A + (size_t)(bm + row) * K + k0 + cg);
            As[cg + 0][row] = a.x; As[cg + 1][row] = a.y;
            As[cg + 2][row] = a.z; As[cg + 3][row] = a.w;
            float4 b = *reinterpret_cast<const float4*>(W + (size_t)(bn + row) * K + k0 + cg);
            Bs[cg + 0][row] = b.x; Bs[cg + 1][row] = b.y;
            Bs[cg + 2][row] = b.z; Bs[cg + 3][row] = b.w;
        }
        __syncthreads();

        #pragma unroll
        for (int kk = 0; kk < BK; kk++) {
            float ar[8], br[8];
            const float4* a4 = reinterpret_cast<const float4*>(&As[kk][ty * 8]);
            const float4* b4 = reinterpret_cast<const float4*>(&Bs[kk][tx * 8]);
            float4 a0 = a4[0], a1 = a4[1];
            float4 b0 = b4[0], b1 = b4[1];
            ar[0]=a0.x; ar[1]=a0.y; ar[2]=a0.z; ar[3]=a0.w;
            ar[4]=a1.x; ar[5]=a1.y; ar[6]=a1.z; ar[7]=a1.w;
            br[0]=b0.x; br[1]=b0.y; br[2]=b0.z; br[3]=b0.w;
            br[4]=b1.x; br[5]=b1.y; br[6]=b1.z; br[7]=b1.w;
            #pragma unroll
            for (int i = 0; i < 8; i++)
                #pragma unroll
                for (int j = 0; j < 8; j++)
                    acc[i][j] = fmaf(ar[i], br[j], acc[i][j]);
        }
        __syncthreads();
    }

    // epilogue
    #pragma unroll
    for (int i = 0; i < 8; i++) {
        int gm = bm + ty * 8 + i;
        #pragma unroll
        for (int j = 0; j < 8; j++) {
            int gn = bn + tx * 8 + j;
            float v = acc[i][j];
            if (act == 1) {
                v += bias[gn];
                // softplus = log1p(exp(v)); saturate for large v
                v = (v > 20.f) ? v : log1pf(expf(v));
            }
            C[(size_t)gm * N + gn] = v;
        }
    }
}

// ---------------- depthwise causal conv (K=4) + bias + SiLU ------------------
__global__ void conv_silu_kernel(const float* __restrict__ xssm,
                                 const float* __restrict__ cw,
                                 const float* __restrict__ cb,
                                 float* __restrict__ out)
{
    int idx = blockIdx.x * blockDim.x + threadIdx.x;
    if (idx >= M_ROWS * D_MODEL) return;
    int d = idx % D_MODEL;
    int t = (idx / D_MODEL) % T_SEQ;
    int b = idx / (D_MODEL * T_SEQ);

    float acc = cb[d];
    #pragma unroll
    for (int k = 0; k < D_CONV; k++) {
        int tt = t - (D_CONV - 1) + k;
        if (tt >= 0)
            acc = fmaf(xssm[((size_t)(b * T_SEQ + tt)) * D_MODEL + d], cw[d * D_CONV + k], acc);
    }
    // SiLU
    float s = 1.f / (1.f + __expf(-acc));
    out[idx] = acc * s;
}

// ---------------- B/C projections: (M,768) x (16,768)^T x2 -------------------
__global__ __launch_bounds__(512)
void bc_gemm_kernel(const float* __restrict__ xc,
                    const float* __restrict__ WB, const float* __restrict__ WC,
                    float* __restrict__ Bm, float* __restrict__ Cm)
{
    int r = threadIdx.x >> 5;              // 0..15 rows in this block
    int c = threadIdx.x & 31;              // 0..31: 0-15 -> B, 16-31 -> C
    size_t row = (size_t)blockIdx.x * 16 + r;

    const float* w = (c < 16) ? (WB + (size_t)c * D_MODEL) : (WC + (size_t)(c - 16) * D_MODEL);
    const float4* x4 = reinterpret_cast<const float4*>(xc + row * D_MODEL);
    const float4* w4 = reinterpret_cast<const float4*>(w);

    float acc = 0.f;
    #pragma unroll 8
    for (int k = 0; k < D_MODEL / 4; k++) {
        float4 a = x4[k], b = w4[k];
        acc = fmaf(a.x, b.x, acc);
        acc = fmaf(a.y, b.y, acc);
        acc = fmaf(a.z, b.z, acc);
        acc = fmaf(a.w, b.w, acc);
    }
    if (c < 16) Bm[row * D_STATE + c] = acc;
    else        Cm[row * D_STATE + (c - 16)] = acc;
}

// ---------------- scan helpers ------------------------------------------------
__device__ __forceinline__ void load_A_and_mode(const float* __restrict__ A_log,
                                                int d, float* A, bool& fast)
{
    #pragma unroll
    for (int n = 0; n < D_STATE; n++) A[n] = -__expf(A_log[d * D_STATE + n]);
    fast = true;
    #pragma unroll
    for (int n = 1; n < D_STATE; n++)
        fast = fast && (fabsf(A[n] - (float)(n + 1) * A[0]) <= 1e-4f * fabsf(A[n]));
}

// pass 1: per-chunk local scan from h=0; emit end-state and cumulative decay
__global__ __launch_bounds__(256)
void scan_pass1(const float* __restrict__ dt, const float* __restrict__ Bm,
                const float* __restrict__ x,  const float* __restrict__ A_log,
                float* __restrict__ hend, float* __restrict__ Pp)
{
    __shared__ float sB[TCH * D_STATE];
    int d  = blockIdx.x * blockDim.x + threadIdx.x;   // 0..767
    int ch = blockIdx.y;
    int b  = blockIdx.z;
    int t0 = ch * TCH;

    const float* Bsrc = Bm + ((size_t)(b * T_SEQ + t0)) * D_STATE;
    for (int i = threadIdx.x; i < TCH * D_STATE; i += blockDim.x) sB[i] = Bsrc[i];
    __syncthreads();

    float A[D_STATE]; bool fast;
    load_A_and_mode(A_log, d, A, fast);

    float h[D_STATE], P[D_STATE];
    #pragma unroll
    for (int n = 0; n < D_STATE; n++) { h[n] = 0.f; P[n] = 1.f; }

    const float* dtp = dt + ((size_t)(b * T_SEQ + t0)) * D_MODEL + d;
    const float* xp  = x  + ((size_t)(b * T_SEQ + t0)) * D_MODEL + d;

    for (int t = 0; t < TCH; t++) {
        float dtv = dtp[(size_t)t * D_MODEL];
        float xv  = xp [(size_t)t * D_MODEL];
        float u   = xv * dtv;
        const float* Bt = sB + t * D_STATE;
        if (fast) {
            float p  = __expf(A[0] * dtv);
            float pw = 1.f;
            #pragma unroll
            for (int n = 0; n < D_STATE; n++) {
                pw *= p;
                h[n] = fmaf(h[n], pw, u * Bt[n]);
                P[n] *= pw;
            }
        } else {
            #pragma unroll
            for (int n = 0; n < D_STATE; n++) {
                float pw = __expf(A[n] * dtv);
                h[n] = fmaf(h[n], pw, u * Bt[n]);
                P[n] *= pw;
            }
        }
    }
    size_t base = ((size_t)(b * NCH + ch) * D_STATE) * D_MODEL + d;
    #pragma unroll
    for (int n = 0; n < D_STATE; n++) {
        hend[base + (size_t)n * D_MODEL] = h[n];
        Pp  [base + (size_t)n * D_MODEL] = P[n];
    }
}

// pass 2: sequential combine over chunks -> chunk-entry states
__global__ void scan_combine(const float* __restrict__ hend, const float* __restrict__ Pp,
                             float* __restrict__ sin_)
{
    int idx = blockIdx.x * blockDim.x + threadIdx.x;       // over B*N*D
    if (idx >= B_SZ * D_STATE * D_MODEL) return;
    int d = idx % D_MODEL;
    int n = (idx / D_MODEL) % D_STATE;
    int b = idx / (D_MODEL * D_STATE);

    float s = 0.f;
    for (int ch = 0; ch < NCH; ch++) {
        size_t off = ((size_t)(b * NCH + ch) * D_STATE + n) * D_MODEL + d;
        sin_[off] = s;
        s = fmaf(Pp[off], s, hend[off]);
    }
}

// pass 3: replay chunks with correct entry state; emit y + residual
__global__ __launch_bounds__(256)
void scan_pass3(const float* __restrict__ dt, const float* __restrict__ Bm,
                const float* __restrict__ Cm, const float* __restrict__ x,
                const float* __restrict__ A_log, const float* __restrict__ Dp,
                const float* __restrict__ sin_, float* __restrict__ y)
{
    __shared__ float sB[TCH * D_STATE];
    __shared__ float sC[TCH * D_STATE];
    int d  = blockIdx.x * blockDim.x + threadIdx.x;
    int ch = blockIdx.y;
    int b  = blockIdx.z;
    int t0 = ch * TCH;

    const float* Bsrc = Bm + ((size_t)(b * T_SEQ + t0)) * D_STATE;
    const float* Csrc = Cm + ((size_t)(b * T_SEQ + t0)) * D_STATE;
    for (int i = threadIdx.x; i < TCH * D_STATE; i += blockDim.x) {
        sB[i] = Bsrc[i];
        sC[i] = Csrc[i];
    }
    __syncthreads();

    float A[D_STATE]; bool fast;
    load_A_and_mode(A_log, d, A, fast);

    float h[D_STATE];
    size_t base = ((size_t)(b * NCH + ch) * D_STATE) * D_MODEL + d;
    #pragma unroll
    for (int n = 0; n < D_STATE; n++) h[n] = sin_[base + (size_t)n * D_MODEL];

    float dpar = Dp[d];
    const float* dtp = dt + ((size_t)(b * T_SEQ + t0)) * D_MODEL + d;
    const float* xp  = x  + ((size_t)(b * T_SEQ + t0)) * D_MODEL + d;
    float* yp        = y  + ((size_t)(b * T_SEQ + t0)) * D_MODEL + d;

    for (int t = 0; t < TCH; t++) {
        float dtv = dtp[(size_t)t * D_MODEL];
        float xv  = xp [(size_t)t * D_MODEL];
        float u   = xv * dtv;
        const float* Bt = sB + t * D_STATE;
        const float* Ct = sC + t * D_STATE;
        float acc = 0.f;
        if (fast) {
            float p  = __expf(A[0] * dtv);
            float pw = 1.f;
            #pragma unroll
            for (int n = 0; n < D_STATE; n++) {
                pw *= p;
                h[n] = fmaf(h[n], pw, u * Bt[n]);
                acc  = fmaf(h[n], Ct[n], acc);
            }
        } else {
            #pragma unroll
            for (int n = 0; n < D_STATE; n++) {
                float pw = __expf(A[n] * dtv);
                h[n] = fmaf(h[n], pw, u * Bt[n]);
                acc  = fmaf(h[n], Ct[n], acc);
            }
        }
        yp[(size_t)t * D_MODEL] = fmaf(xv, dpar, acc);
    }
}

// ---------------- launch ------------------------------------------------------
extern "C" void kernel_launch(void* const* d_in, const int* in_sizes, int n_in,
                              void* d_out, int out_size)
{
    const float* x      = (const float*)d_in[0];
    const float* W_in   = (const float*)d_in[1];
    const float* conv_w = (const float*)d_in[2];
    const float* conv_b = (const float*)d_in[3];
    const float* W_dt   = (const float*)d_in[4];
    const float* b_dt   = (const float*)d_in[5];
    const float* A_log  = (const float*)d_in[6];
    const float* D_par  = (const float*)d_in[7];
    const float* W_B    = (const float*)d_in[8];
    const float* W_C    = (const float*)d_in[9];
    float* y = (float*)d_out;

    float *xssm, *xconv, *dtb, *Bm, *Cm, *hend, *Pp, *sin_;
    cudaGetSymbolAddress((void**)&xssm,  g_xssm);
    cudaGetSymbolAddress((void**)&xconv, g_xconv);
    cudaGetSymbolAddress((void**)&dtb,   g_dt);
    cudaGetSymbolAddress((void**)&Bm,    g_Bm);
    cudaGetSymbolAddress((void**)&Cm,    g_Cm);
    cudaGetSymbolAddress((void**)&hend,  g_hend);
    cudaGetSymbolAddress((void**)&Pp,    g_Pp);
    cudaGetSymbolAddress((void**)&sin_,  g_sin);

    // 1) x_ssm = x @ W_in[:768].T   (the z half of the in-proj is dead code)
    dim3 gemm_grid(D_MODEL / BN, M_ROWS / BM);
    gemm_tn_kernel<<<gemm_grid, 256>>>(x, W_in, nullptr, xssm,
                                       M_ROWS, D_MODEL, D_MODEL, 0);

    // 2) depthwise causal conv + bias + SiLU
    int total = M_ROWS * D_MODEL;
    conv_silu_kernel<<<(total + 255) / 256, 256>>>(xssm, conv_w, conv_b, xconv);

    // 3) dt = softplus(x_conv @ W_dt.T + b_dt)
    gemm_tn_kernel<<<gemm_grid, 256>>>(xconv, W_dt, b_dt, dtb,
                                       M_ROWS, D_MODEL, D_MODEL, 1);

    // 4) Bm = x_conv @ W_B.T ; Cm = x_conv @ W_C.T
    bc_gemm_kernel<<<M_ROWS / 16, 512>>>(xconv, W_B, W_C, Bm, Cm);

    // 5-7) chunked associative scan
    dim3 scan_grid(D_MODEL / 256, NCH, B_SZ);
    scan_pass1<<<scan_grid, 256>>>(dtb, Bm, x, A_log, hend, Pp);
    scan_combine<<<(B_SZ * D_STATE * D_MODEL + 255) / 256, 256>>>(hend, Pp, sin_);
    scan_pass3<<<scan_grid, 256>>>(dtb, Bm, Cm, x, A_log, D_par, sin_, y);
}

// round 3
// speedup vs baseline: 2.7498x; 2.7498x over previous
#include <cuda_runtime.h>
#include <cstdint>

// Problem constants
#define B_SZ 8
#define T_SEQ 2048
#define D_MODEL 768
#define D_STATE 16
#define D_CONV 4
#define M_ROWS (B_SZ * T_SEQ)          // 16384
#define NCH 16                          // scan chunks
#define TCH (T_SEQ / NCH)               // 128 steps per chunk

// ---------------- scratch (__device__ globals; no runtime alloc) -------------
__device__ float g_xssm [M_ROWS * D_MODEL];
__device__ float g_xconv[M_ROWS * D_MODEL];
__device__ float g_dt   [M_ROWS * D_MODEL];
__device__ float g_Bm   [M_ROWS * D_STATE];
__device__ float g_Cm   [M_ROWS * D_STATE];
__device__ float g_hend [B_SZ * NCH * D_STATE * D_MODEL];
__device__ float g_Pp   [B_SZ * NCH * D_STATE * D_MODEL];
__device__ float g_sin  [B_SZ * NCH * D_STATE * D_MODEL];

// ============================ PTX helpers =====================================
__device__ __forceinline__ uint32_t smem_u32(const void* p) {
    uint32_t a;
    asm("{ .reg .u64 t; cvta.to.shared.u64 t, %1; cvt.u32.u64 %0, t; }" : "=r"(a) : "l"(p));
    return a;
}
__device__ __forceinline__ uint32_t f2tf32(float x) {
    uint32_t r;
    asm("cvt.rna.tf32.f32 %0, %1;" : "=r"(r) : "f"(x));
    return r;
}
__device__ __forceinline__ void ldsm_x4(uint32_t addr, uint32_t& r0, uint32_t& r1,
                                        uint32_t& r2, uint32_t& r3) {
    asm volatile("ldmatrix.sync.aligned.m8n8.x4.shared.b16 {%0,%1,%2,%3}, [%4];"
                 : "=r"(r0), "=r"(r1), "=r"(r2), "=r"(r3) : "r"(addr));
}
__device__ __forceinline__ void mma_tf32(float& c0, float& c1, float& c2, float& c3,
                                         uint32_t a0, uint32_t a1, uint32_t a2, uint32_t a3,
                                         uint32_t b0, uint32_t b1) {
    asm volatile("mma.sync.aligned.m16n8k8.row.col.f32.tf32.tf32.f32 "
                 "{%0,%1,%2,%3}, {%4,%5,%6,%7}, {%8,%9}, {%0,%1,%2,%3};"
                 : "+f"(c0), "+f"(c1), "+f"(c2), "+f"(c3)
                 : "r"(a0), "r"(a1), "r"(a2), "r"(a3), "r"(b0), "r"(b1));
}

// ===================== tf32 mma.sync GEMM: C = A[M,768] * W[768,768]^T =========
// tile: 128x128, BK=16, double-buffered static smem (40 KB). 8 warps, each 64x32.
// act: 0 = none, 1 = softplus(v + bias)
#define GK 768
#define CHK 16
#define NKCH (GK / CHK)                 // 48
#define SROW 20                         // 16 + 4 pad floats (80B row, LDSM conflict-free)

__global__ __launch_bounds__(256, 2)
void gemm_tc_tf32(const float* __restrict__ A, const float* __restrict__ W,
                  const float* __restrict__ bias, float* __restrict__ C, int act)
{
    __shared__ float As[2][128][SROW];
    __shared__ float Ws[2][128][SROW];

    const int tid  = threadIdx.x;
    const int wid  = tid >> 5;
    const int lane = tid & 31;
    const int bn   = blockIdx.x * 128;
    const int bm   = blockIdx.y * 128;
    const int wm   = (wid & 1) * 64;    // warp m-offset within tile
    const int wn   = (wid >> 1) * 32;   // warp n-offset within tile

    float acc[4][4][4];                 // [mf][nf][c0..c3]
    #pragma unroll
    for (int i = 0; i < 4; i++)
        #pragma unroll
        for (int j = 0; j < 4; j++)
            #pragma unroll
            for (int c = 0; c < 4; c++) acc[i][j][c] = 0.f;

    // gmem load pattern: 512 float4 per matrix per chunk / 256 thr = 2 each
    int gr[2], gc[2];
    #pragma unroll
    for (int i = 0; i < 2; i++) { int idx = tid + i * 256; gr[i] = idx >> 2; gc[i] = (idx & 3) * 4; }

    const float* Aptr = A + (size_t)(bm + gr[0]) * GK + gc[0];
    const float* Wptr = W + (size_t)(bn + gr[0]) * GK + gc[0];
    const size_t gstep = (size_t)64 * GK;   // gr[1]-gr[0] = 64 rows

    float4 ra[2], rw[2];
    auto ldg = [&](int k) {
        int k0 = k * CHK;
        ra[0] = *reinterpret_cast<const float4*>(Aptr + k0);
        ra[1] = *reinterpret_cast<const float4*>(Aptr + gstep + k0);
        rw[0] = *reinterpret_cast<const float4*>(Wptr + k0);
        rw[1] = *reinterpret_cast<const float4*>(Wptr + gstep + k0);
    };
    auto sts = [&](int buf) {
        #pragma unroll
        for (int i = 0; i < 2; i++) {
            int row = gr[0] + i * 64;
            float* pa = &As[buf][row][gc[0]];
            float* pw = &Ws[buf][row][gc[0]];
            uint4 va = make_uint4(f2tf32(ra[i].x), f2tf32(ra[i].y), f2tf32(ra[i].z), f2tf32(ra[i].w));
            uint4 vw = make_uint4(f2tf32(rw[i].x), f2tf32(rw[i].y), f2tf32(rw[i].z), f2tf32(rw[i].w));
            *reinterpret_cast<uint4*>(pa) = va;
            *reinterpret_cast<uint4*>(pw) = vw;
        }
    };

    // ldmatrix per-lane addressing: row = (lane&15), col-half = (lane>>4)*4
    const int lrow = lane & 15;
    const int lcol = (lane >> 4) * 4;

    // prologue
    ldg(0); sts(0);
    ldg(1);
    __syncthreads();

    for (int k = 0; k < NKCH; k++) {
        int buf = k & 1;
        uint32_t aBase = smem_u32(&As[buf][wm + lrow][lcol]);
        uint32_t bBase = smem_u32(&Ws[buf][wn + lrow][lcol]);

        #pragma unroll
        for (int ks = 0; ks < 2; ks++) {
            uint32_t koff = (uint32_t)(ks * 8 * 4);
            // B: two x4 loads cover n32 x k8
            uint32_t b00, b01, b10, b11, b20, b21, b30, b31;
            ldsm_x4(bBase + koff, b00, b10, b01, b11);                      // n rows 0-15
            ldsm_x4(bBase + koff + 16u * SROW * 4u, b20, b30, b21, b31);    // n rows 16-31
            #pragma unroll
            for (int mf = 0; mf < 4; mf++) {
                uint32_t a0, a1, a2, a3;
                ldsm_x4(aBase + koff + (uint32_t)(mf * 16 * SROW * 4), a0, a1, a2, a3);
                mma_tf32(acc[mf][0][0], acc[mf][0][1], acc[mf][0][2], acc[mf][0][3],
                         a0, a1, a2, a3, b00, b01);
                mma_tf32(acc[mf][1][0], acc[mf][1][1], acc[mf][1][2], acc[mf][1][3],
                         a0, a1, a2, a3, b10, b11);
                mma_tf32(acc[mf][2][0], acc[mf][2][1], acc[mf][2][2], acc[mf][2][3],
                         a0, a1, a2, a3, b20, b21);
                mma_tf32(acc[mf][3][0], acc[mf][3][1], acc[mf][3][2], acc[mf][3][3],
                         a0, a1, a2, a3, b30, b31);
            }
        }

        if (k + 1 < NKCH) {
            sts((k + 1) & 1);            // safe: that buf last read at mma(k-1)
            if (k + 2 < NKCH) ldg(k + 2);
            __syncthreads();
        }
    }

    // epilogue: c0/c1 = (row, col), (row, col+1); c2/c3 = row+8
    const int erow = lane >> 2;
    const int ecol = (lane & 3) * 2;
    #pragma unroll
    for (int mf = 0; mf < 4; mf++) {
        int row = bm + wm + mf * 16 + erow;
        #pragma unroll
        for (int nf = 0; nf < 4; nf++) {
            int col = bn + wn + nf * 8 + ecol;
            float v0 = acc[mf][nf][0], v1 = acc[mf][nf][1];
            float v2 = acc[mf][nf][2], v3 = acc[mf][nf][3];
            if (act == 1) {
                float b0 = bias[col], b1 = bias[col + 1];
                v0 += b0; v1 += b1; v2 += b0; v3 += b1;
                v0 = (v0 > 20.f) ? v0 : log1pf(__expf(v0));
                v1 = (v1 > 20.f) ? v1 : log1pf(__expf(v1));
                v2 = (v2 > 20.f) ? v2 : log1pf(__expf(v2));
                v3 = (v3 > 20.f) ? v3 : log1pf(__expf(v3));
            }
            *reinterpret_cast<float2*>(C + (size_t)row * D_MODEL + col)       = make_float2(v0, v1);
            *reinterpret_cast<float2*>(C + (size_t)(row + 8) * D_MODEL + col) = make_float2(v2, v3);
        }
    }
}

// ---------------- depthwise causal conv (K=4) + bias + SiLU ------------------
__global__ void conv_silu_kernel(const float* __restrict__ xssm,
                                 const float* __restrict__ cw,
                                 const float* __restrict__ cb,
                                 float* __restrict__ out)
{
    int idx = blockIdx.x * blockDim.x + threadIdx.x;
    if (idx >= M_ROWS * D_MODEL) return;
    int d = idx % D_MODEL;
    int t = (idx / D_MODEL) % T_SEQ;

    float acc = cb[d];
    #pragma unroll
    for (int k = 0; k < D_CONV; k++) {
        int rel = k - (D_CONV - 1);            // -3..0
        if (t + rel >= 0)
            acc = fmaf(xssm[(long)idx + (long)rel * D_MODEL], cw[d * D_CONV + k], acc);
    }
    float s = 1.f / (1.f + __expf(-acc));
    out[idx] = acc * s;
}

// ---------------- B/C projections: smem-tiled --------------------------------
__global__ __launch_bounds__(256)
void bc_gemm2(const float* __restrict__ xc,
              const float* __restrict__ WB, const float* __restrict__ WC,
              float* __restrict__ Bm, float* __restrict__ Cm)
{
    __shared__ float sX[128][68];
    __shared__ float sW[64][32];

    const int tid = threadIdx.x;
    const int r = tid >> 1;
    const int half = tid & 1;
    const size_t row0 = (size_t)blockIdx.x * 128;

    float acc[16];
    #pragma unroll
    for (int n = 0; n < 16; n++) acc[n] = 0.f;

    for (int k0 = 0; k0 < D_MODEL; k0 += 64) {
        #pragma unroll
        for (int i = 0; i < 8; i++) {
            int idx = tid + i * 256;
            int rr = idx >> 4, c4 = idx & 15;
            float4 v = *reinterpret_cast<const float4*>(xc + (row0 + rr) * D_MODEL + k0 + c4 * 4);
            sX[rr][c4 * 4 + 0] = v.x; sX[rr][c4 * 4 + 1] = v.y;
            sX[rr][c4 * 4 + 2] = v.z; sX[rr][c4 * 4 + 3] = v.w;
        }
        #pragma unroll
        for (int i = 0; i < 2; i++) {
            int idx = tid + i * 256;
            int j = idx >> 4, c4 = idx & 15;
            const float* ws = (j < 16) ? (WB + (size_t)j * D_MODEL) : (WC + (size_t)(j - 16) * D_MODEL);
            float4 v = *reinterpret_cast<const float4*>(ws + k0 + c4 * 4);
            sW[c4 * 4 + 0][j] = v.x; sW[c4 * 4 + 1][j] = v.y;
            sW[c4 * 4 + 2][j] = v.z; sW[c4 * 4 + 3][j] = v.w;
        }
        __syncthreads();

        #pragma unroll 8
        for (int kk = 0; kk < 64; kk++) {
            float xv = sX[r][kk];
            const float4* w4 = reinterpret_cast<const float4*>(&sW[kk][half * 16]);
            float4 w0 = w4[0], w1 = w4[1], w2 = w4[2], w3 = w4[3];
            acc[0]  = fmaf(xv, w0.x, acc[0]);  acc[1]  = fmaf(xv, w0.y, acc[1]);
            acc[2]  = fmaf(xv, w0.z, acc[2]);  acc[3]  = fmaf(xv, w0.w, acc[3]);
            acc[4]  = fmaf(xv, w1.x, acc[4]);  acc[5]  = fmaf(xv, w1.y, acc[5]);
            acc[6]  = fmaf(xv, w1.z, acc[6]);  acc[7]  = fmaf(xv, w1.w, acc[7]);
            acc[8]  = fmaf(xv, w2.x, acc[8]);  acc[9]  = fmaf(xv, w2.y, acc[9]);
            acc[10] = fmaf(xv, w2.z, acc[10]); acc[11] = fmaf(xv, w2.w, acc[11]);
            acc[12] = fmaf(xv, w3.x, acc[12]); acc[13] = fmaf(xv, w3.y, acc[13]);
            acc[14] = fmaf(xv, w3.z, acc[14]); acc[15] = fmaf(xv, w3.w, acc[15]);
        }
        __syncthreads();
    }
    float* dst = (half ? Cm : Bm) + (row0 + r) * D_STATE;
    #pragma unroll
    for (int n = 0; n < 4; n++)
        *reinterpret_cast<float4*>(dst + n * 4) =
            make_float4(acc[n*4+0], acc[n*4+1], acc[n*4+2], acc[n*4+3]);
}

// ---------------- scan helpers ------------------------------------------------
__device__ __forceinline__ void load_A_and_mode(const float* __restrict__ A_log,
                                                int d, float* A, bool& fast)
{
    #pragma unroll
    for (int n = 0; n < D_STATE; n++) A[n] = -__expf(A_log[d * D_STATE + n]);
    fast = true;
    #pragma unroll
    for (int n = 1; n < D_STATE; n++)
        fast = fast && (fabsf(A[n] - (float)(n + 1) * A[0]) <= 1e-4f * fabsf(A[n]));
}

// log-depth powers: pw[n] = p^(n+1)
__device__ __forceinline__ void powers16(float p1, float* pw)
{
    float p2 = p1 * p1, p4 = p2 * p2, p8 = p4 * p4;
    pw[0] = p1;        pw[1] = p2;        pw[2] = p2 * p1;   pw[3] = p4;
    pw[4] = p4 * p1;   pw[5] = p4 * p2;   pw[6] = p4 * pw[2]; pw[7] = p8;
    pw[8] = p8 * p1;   pw[9] = p8 * p2;   pw[10] = p8 * pw[2]; pw[11] = p8 * p4;
    pw[12] = p8 * pw[4]; pw[13] = p8 * pw[5]; pw[14] = p8 * pw[6]; pw[15] = p8 * p8;
}

// pass 1: per-chunk local scan from h=0; emit end-state and cumulative decay
__global__ __launch_bounds__(256)
void scan_pass1(const float* __restrict__ dt, const float* __restrict__ Bm,
                const float* __restrict__ x,  const float* __restrict__ A_log,
                float* __restrict__ hend, float* __restrict__ Pp)
{
    __shared__ float sB[TCH * D_STATE];
    int d  = blockIdx.x * blockDim.x + threadIdx.x;
    int ch = blockIdx.y;
    int b  = blockIdx.z;
    int t0 = ch * TCH;

    {
        const float4* src = reinterpret_cast<const float4*>(Bm + ((size_t)(b * T_SEQ + t0)) * D_STATE);
        float4* dst = reinterpret_cast<float4*>(sB);
        for (int i = threadIdx.x; i < TCH * D_STATE / 4; i += blockDim.x) dst[i] = src[i];
    }
    __syncthreads();

    float A[D_STATE]; bool fast;
    load_A_and_mode(A_log, d, A, fast);

    float h[D_STATE];
    #pragma unroll
    for (int n = 0; n < D_STATE; n++) h[n] = 0.f;

    const float* dtp = dt + ((size_t)(b * T_SEQ + t0)) * D_MODEL + d;
    const float* xp  = x  + ((size_t)(b * T_SEQ + t0)) * D_MODEL + d;

    size_t base = ((size_t)(b * NCH + ch) * D_STATE) * D_MODEL + d;

    if (fast) {
        float S = 0.f;
        for (int t = 0; t < TCH; t++) {
            float dtv = dtp[(size_t)t * D_MODEL];
            float xv  = xp [(size_t)t * D_MODEL];
            float u   = xv * dtv;
            S += dtv;
            float pw[16];
            powers16(__expf(A[0] * dtv), pw);
            const float* Bt = sB + t * D_STATE;
            #pragma unroll
            for (int n = 0; n < D_STATE; n++)
                h[n] = fmaf(h[n], pw[n], u * Bt[n]);
        }
        float pw[16];
        powers16(__expf(A[0] * S), pw);
        #pragma unroll
        for (int n = 0; n < D_STATE; n++) {
            hend[base + (size_t)n * D_MODEL] = h[n];
            Pp  [base + (size_t)n * D_MODEL] = pw[n];
        }
    } else {
        float P[D_STATE];
        #pragma unroll
        for (int n = 0; n < D_STATE; n++) P[n] = 1.f;
        for (int t = 0; t < TCH; t++) {
            float dtv = dtp[(size_t)t * D_MODEL];
            float xv  = xp [(size_t)t * D_MODEL];
            float u   = xv * dtv;
            const float* Bt = sB + t * D_STATE;
            #pragma unroll
            for (int n = 0; n < D_STATE; n++) {
                float pw = __expf(A[n] * dtv);
                h[n] = fmaf(h[n], pw, u * Bt[n]);
                P[n] *= pw;
            }
        }
        #pragma unroll
        for (int n = 0; n < D_STATE; n++) {
            hend[base + (size_t)n * D_MODEL] = h[n];
            Pp  [base + (size_t)n * D_MODEL] = P[n];
        }
    }
}

// pass 2: sequential combine over chunks -> chunk-entry states
__global__ void scan_combine(const float* __restrict__ hend, const float* __restrict__ Pp,
                             float* __restrict__ sin_)
{
    int idx = blockIdx.x * blockDim.x + threadIdx.x;
    if (idx >= B_SZ * D_STATE * D_MODEL) return;
    int d = idx % D_MODEL;
    int n = (idx / D_MODEL) % D_STATE;
    int b = idx / (D_MODEL * D_STATE);

    float s = 0.f;
    for (int ch = 0; ch < NCH; ch++) {
        size_t off = ((size_t)(b * NCH + ch) * D_STATE + n) * D_MODEL + d;
        sin_[off] = s;
        s = fmaf(Pp[off], s, hend[off]);
    }
}

// pass 3: replay chunks with correct entry state; emit y + residual
__global__ __launch_bounds__(256)
void scan_pass3(const float* __restrict__ dt, const float* __restrict__ Bm,
                const float* __restrict__ Cm, const float* __restrict__ x,
                const float* __restrict__ A_log, const float* __restrict__ Dp,
                const float* __restrict__ sin_, float* __restrict__ y)
{
    __shared__ float sB[TCH * D_STATE];
    __shared__ float sC[TCH * D_STATE];
    int d  = blockIdx.x * blockDim.x + threadIdx.x;
    int ch = blockIdx.y;
    int b  = blockIdx.z;
    int t0 = ch * TCH;

    {
        const float4* srcB = reinterpret_cast<const float4*>(Bm + ((size_t)(b * T_SEQ + t0)) * D_STATE);
        const float4* srcC = reinterpret_cast<const float4*>(Cm + ((size_t)(b * T_SEQ + t0)) * D_STATE);
        float4* dB = reinterpret_cast<float4*>(sB);
        float4* dC = reinterpret_cast<float4*>(sC);
        for (int i = threadIdx.x; i < TCH * D_STATE / 4; i += blockDim.x) { dB[i] = srcB[i]; dC[i] = srcC[i]; }
    }
    __syncthreads();

    float A[D_STATE]; bool fast;
    load_A_and_mode(A_log, d, A, fast);

    float h[D_STATE];
    size_t base = ((size_t)(b * NCH + ch) * D_STATE) * D_MODEL + d;
    #pragma unroll
    for (int n = 0; n < D_STATE; n++) h[n] = sin_[base + (size_t)n * D_MODEL];

    float dpar = Dp[d];
    const float* dtp = dt + ((size_t)(b * T_SEQ + t0)) * D_MODEL + d;
    const float* xp  = x  + ((size_t)(b * T_SEQ + t0)) * D_MODEL + d;
    float* yp        = y  + ((size_t)(b * T_SEQ + t0)) * D_MODEL + d;

    if (fast) {
        for (int t = 0; t < TCH; t++) {
            float dtv = dtp[(size_t)t * D_MODEL];
            float xv  = xp [(size_t)t * D_MODEL];
            float u   = xv * dtv;
            float pw[16];
            powers16(__expf(A[0] * dtv), pw);
            const float* Bt = sB + t * D_STATE;
            const float* Ct = sC + t * D_STATE;
            float acc = 0.f;
            #pragma unroll
            for (int n = 0; n < D_STATE; n++) {
                h[n] = fmaf(h[n], pw[n], u * Bt[n]);
                acc  = fmaf(h[n], Ct[n], acc);
            }
            yp[(size_t)t * D_MODEL] = fmaf(xv, dpar, acc);
        }
    } else {
        for (int t = 0; t < TCH; t++) {
            float dtv = dtp[(size_t)t * D_MODEL];
            float xv  = xp [(size_t)t * D_MODEL];
            float u   = xv * dtv;
            const float* Bt = sB + t * D_STATE;
            const float* Ct = sC + t * D_STATE;
            float acc = 0.f;
            #pragma unroll
            for (int n = 0; n < D_STATE; n++) {
                float pw = __expf(A[n] * dtv);
                h[n] = fmaf(h[n], pw, u * Bt[n]);
                acc  = fmaf(h[n], Ct[n], acc);
            }
            yp[(size_t)t * D_MODEL] = fmaf(xv, dpar, acc);
        }
    }
}

// ---------------- launch ------------------------------------------------------
extern "C" void kernel_launch(void* const* d_in, const int* in_sizes, int n_in,
                              void* d_out, int out_size)
{
    const float* x      = (const float*)d_in[0];
    const float* W_in   = (const float*)d_in[1];
    const float* conv_w = (const float*)d_in[2];
    const float* conv_b = (const float*)d_in[3];
    const float* W_dt   = (const float*)d_in[4];
    const float* b_dt   = (const float*)d_in[5];
    const float* A_log  = (const float*)d_in[6];
    const float* D_par  = (const float*)d_in[7];
    const float* W_B    = (const float*)d_in[8];
    const float* W_C    = (const float*)d_in[9];
    float* y = (float*)d_out;

    float *xssm, *xconv, *dtb, *Bm, *Cm, *hend, *Pp, *sin_;
    cudaGetSymbolAddress((void**)&xssm,  g_xssm);
    cudaGetSymbolAddress((void**)&xconv, g_xconv);
    cudaGetSymbolAddress((void**)&dtb,   g_dt);
    cudaGetSymbolAddress((void**)&Bm,    g_Bm);
    cudaGetSymbolAddress((void**)&Cm,    g_Cm);
    cudaGetSymbolAddress((void**)&hend,  g_hend);
    cudaGetSymbolAddress((void**)&Pp,    g_Pp);
    cudaGetSymbolAddress((void**)&sin_,  g_sin);

    // 1) x_ssm = x @ W_in[:768].T   (z half of in-proj is dead code)
    dim3 gemm_grid(D_MODEL / 128, M_ROWS / 128);
    gemm_tc_tf32<<<gemm_grid, 256>>>(x, W_in, nullptr, xssm, 0);

    // 2) depthwise causal conv + bias + SiLU
    int total = M_ROWS * D_MODEL;
    conv_silu_kernel<<<(total + 255) / 256, 256>>>(xssm, conv_w, conv_b, xconv);

    // 3) dt = softplus(x_conv @ W_dt.T + b_dt)
    gemm_tc_tf32<<<gemm_grid, 256>>>(xconv, W_dt, b_dt, dtb, 1);

    // 4) Bm = x_conv @ W_B.T ; Cm = x_conv @ W_C.T
    bc_gemm2<<<M_ROWS / 128, 256>>>(xconv, W_B, W_C, Bm, Cm);

    // 5-7) chunked associative scan
    dim3 scan_grid(D_MODEL / 256, NCH, B_SZ);
    scan_pass1<<<scan_grid, 256>>>(dtb, Bm, x, A_log, hend, Pp);
    scan_combine<<<(B_SZ * D_STATE * D_MODEL + 255) / 256, 256>>>(hend, Pp, sin_);
    scan_pass3<<<scan_grid, 256>>>(dtb, Bm, Cm, x, A_log, D_par, sin_, y);
}

// round 4
// speedup vs baseline: 4.0770x; 1.4827x over previous
#include <cuda_runtime.h>
#include <cuda_bf16.h>
#include <cstdint>

// Problem constants
#define B_SZ 8
#define T_SEQ 2048
#define D_MODEL 768
#define D_STATE 16
#define D_CONV 4
#define M_ROWS (B_SZ * T_SEQ)          // 16384
#define NCH 16                          // scan chunks
#define TCH (T_SEQ / NCH)               // 128 steps per chunk
#define NCAT 896                        // padded fused-GEMM2 N (768 dt + 16 B + 16 C + 96 pad)

// ---------------- scratch (__device__ globals; no runtime alloc) -------------
__device__ __nv_bfloat16 g_xbf     [M_ROWS * D_MODEL];
__device__ __nv_bfloat16 g_xssm_bf [M_ROWS * D_MODEL];
__device__ __nv_bfloat16 g_xconv_bf[M_ROWS * D_MODEL];
__device__ __nv_bfloat16 g_Win_bf  [D_MODEL * D_MODEL];
__device__ __nv_bfloat16 g_Wcat_bf [NCAT * D_MODEL];
__device__ float g_dt   [M_ROWS * D_MODEL];
__device__ float g_Bm   [M_ROWS * D_STATE];
__device__ float g_Cm   [M_ROWS * D_STATE];
__device__ float g_hend [B_SZ * NCH * D_STATE * D_MODEL];
__device__ float g_Pp   [B_SZ * NCH * D_STATE * D_MODEL];
__device__ float g_sin  [B_SZ * NCH * D_STATE * D_MODEL];

// ============================ PTX helpers =====================================
__device__ __forceinline__ uint32_t smem_u32(const void* p) {
    uint32_t a;
    asm("{ .reg .u64 t; cvta.to.shared.u64 t, %1; cvt.u32.u64 %0, t; }" : "=r"(a) : "l"(p));
    return a;
}
__device__ __forceinline__ void ldsm_x4(uint32_t addr, uint32_t& r0, uint32_t& r1,
                                        uint32_t& r2, uint32_t& r3) {
    asm volatile("ldmatrix.sync.aligned.m8n8.x4.shared.b16 {%0,%1,%2,%3}, [%4];"
                 : "=r"(r0), "=r"(r1), "=r"(r2), "=r"(r3) : "r"(addr));
}
__device__ __forceinline__ void mma_bf16(float* c,
                                         uint32_t a0, uint32_t a1, uint32_t a2, uint32_t a3,
                                         uint32_t b0, uint32_t b1) {
    asm volatile("mma.sync.aligned.m16n8k16.row.col.f32.bf16.bf16.f32 "
                 "{%0,%1,%2,%3}, {%4,%5,%6,%7}, {%8,%9}, {%0,%1,%2,%3};"
                 : "+f"(c[0]), "+f"(c[1]), "+f"(c[2]), "+f"(c[3])
                 : "r"(a0), "r"(a1), "r"(a2), "r"(a3), "r"(b0), "r"(b1));
}
__device__ __forceinline__ __nv_bfloat16 f2bf(float x) { return __float2bfloat16_rn(x); }

// ===================== bf16 mma.sync GEMM =====================================
// C[M, N] = A[M, 768](bf16) * W[N, 768](bf16)^T, fp32 accumulate.
// tile 128x128, BK=32, double-buffered static smem. 8 warps, each 64x32.
// mode 0: write bf16 to outBF (no act).
// mode 1: fused epilogue: cols <768 -> softplus(v + bias) into outDT (fp32);
//         cols 768..783 -> Bm; 784..799 -> Cm; >=800 discard.
#define GK 768
#define CHKB 32
#define NKB (GK / CHKB)                 // 24
#define SRB 40                          // 32 + 8 pad bf16 (80B row; LDSM conflict-free)

__global__ __launch_bounds__(256, 2)
void gemm_bf16(const __nv_bfloat16* __restrict__ A, const __nv_bfloat16* __restrict__ W,
               const float* __restrict__ bias, __nv_bfloat16* __restrict__ outBF,
               float* __restrict__ outDT, float* __restrict__ Bm, float* __restrict__ Cm,
               int mode)
{
    __shared__ __align__(16) __nv_bfloat16 As[2][128][SRB];
    __shared__ __align__(16) __nv_bfloat16 Ws[2][128][SRB];

    const int tid  = threadIdx.x;
    const int wid  = tid >> 5;
    const int lane = tid & 31;
    const int bn   = blockIdx.x * 128;
    const int bm   = blockIdx.y * 128;
    const int wm   = (wid & 1) * 64;
    const int wn   = (wid >> 1) * 32;

    float acc[4][4][4];
    #pragma unroll
    for (int i = 0; i < 4; i++)
        #pragma unroll
        for (int j = 0; j < 4; j++)
            #pragma unroll
            for (int c = 0; c < 4; c++) acc[i][j][c] = 0.f;

    // gmem load: per chunk 128x32 bf16 = 512 x 16B per matrix; 2 LDG.128/thread
    const int r0 = tid >> 2;              // 0..63
    const int c8 = (tid & 3) * 8;         // bf16 elem offset 0,8,16,24
    const __nv_bfloat16* Aptr = A + (size_t)(bm + r0) * GK + c8;
    const __nv_bfloat16* Wptr = W + (size_t)(bn + r0) * GK + c8;
    const size_t gstep = (size_t)64 * GK;

    uint4 ra[2], rw[2];
    auto ldg = [&](int k) {
        int k0 = k * CHKB;
        ra[0] = *reinterpret_cast<const uint4*>(Aptr + k0);
        ra[1] = *reinterpret_cast<const uint4*>(Aptr + gstep + k0);
        rw[0] = *reinterpret_cast<const uint4*>(Wptr + k0);
        rw[1] = *reinterpret_cast<const uint4*>(Wptr + gstep + k0);
    };
    auto sts = [&](int buf) {
        *reinterpret_cast<uint4*>(&As[buf][r0][c8])      = ra[0];
        *reinterpret_cast<uint4*>(&As[buf][r0 + 64][c8]) = ra[1];
        *reinterpret_cast<uint4*>(&Ws[buf][r0][c8])      = rw[0];
        *reinterpret_cast<uint4*>(&Ws[buf][r0 + 64][c8]) = rw[1];
    };

    // ldmatrix lane addressing
    const int arow = lane & 15;                       // A: rows m0..15
    const int ak   = (lane >> 4) * 8;                 // A: k half
    const int brow = ((lane >> 4) * 8) + (lane & 7);  // B: n row within 16
    const int bk   = ((lane >> 3) & 1) * 8;           // B: k half

    ldg(0); sts(0);
    ldg(1);
    __syncthreads();

    for (int k = 0; k < NKB; k++) {
        int buf = k & 1;
        #pragma unroll
        for (int ks = 0; ks < 2; ks++) {
            int k0e = ks * 16;
            // B fragments: two ldsm.x4 cover n32 x k16 -> frags nf=0..3 (b0,b1 each)
            uint32_t bf[4][2];
            {
                uint32_t addr0 = smem_u32(&Ws[buf][wn + brow][k0e + bk]);
                uint32_t addr1 = smem_u32(&Ws[buf][wn + 16 + brow][k0e + bk]);
                ldsm_x4(addr0, bf[0][0], bf[0][1], bf[1][0], bf[1][1]);
                ldsm_x4(addr1, bf[2][0], bf[2][1], bf[3][0], bf[3][1]);
            }
            #pragma unroll
            for (int mf = 0; mf < 4; mf++) {
                uint32_t a0, a1, a2, a3;
                ldsm_x4(smem_u32(&As[buf][wm + mf * 16 + arow][k0e + ak]), a0, a1, a2, a3);
                #pragma unroll
                for (int nf = 0; nf < 4; nf++)
                    mma_bf16(acc[mf][nf], a0, a1, a2, a3, bf[nf][0], bf[nf][1]);
            }
        }
        if (k + 1 < NKB) {
            sts((k + 1) & 1);
            if (k + 2 < NKB) ldg(k + 2);
            __syncthreads();
        }
    }

    // epilogue: c0/c1 = (row, col/col+1); c2/c3 = row+8
    const int erow = lane >> 2;
    const int ecol = (lane & 3) * 2;
    #pragma unroll
    for (int mf = 0; mf < 4; mf++) {
        int row = bm + wm + mf * 16 + erow;
        #pragma unroll
        for (int nf = 0; nf < 4; nf++) {
            int col = bn + wn + nf * 8 + ecol;
            float v0 = acc[mf][nf][0], v1 = acc[mf][nf][1];
            float v2 = acc[mf][nf][2], v3 = acc[mf][nf][3];
            if (mode == 0) {
                __nv_bfloat162 p0 = { f2bf(v0), f2bf(v1) };
                __nv_bfloat162 p1 = { f2bf(v2), f2bf(v3) };
                *reinterpret_cast<__nv_bfloat162*>(outBF + (size_t)row * D_MODEL + col)       = p0;
                *reinterpret_cast<__nv_bfloat162*>(outBF + (size_t)(row + 8) * D_MODEL + col) = p1;
            } else if (col < 768) {
                float b0 = bias[col], b1 = bias[col + 1];
                v0 += b0; v1 += b1; v2 += b0; v3 += b1;
                v0 = (v0 > 20.f) ? v0 : log1pf(__expf(v0));
                v1 = (v1 > 20.f) ? v1 : log1pf(__expf(v1));
                v2 = (v2 > 20.f) ? v2 : log1pf(__expf(v2));
                v3 = (v3 > 20.f) ? v3 : log1pf(__expf(v3));
                *reinterpret_cast<float2*>(outDT + (size_t)row * D_MODEL + col)       = make_float2(v0, v1);
                *reinterpret_cast<float2*>(outDT + (size_t)(row + 8) * D_MODEL + col) = make_float2(v2, v3);
            } else if (col < 784) {
                int n = col - 768;
                *reinterpret_cast<float2*>(Bm + (size_t)row * D_STATE + n)       = make_float2(v0, v1);
                *reinterpret_cast<float2*>(Bm + (size_t)(row + 8) * D_STATE + n) = make_float2(v2, v3);
            } else if (col < 800) {
                int n = col - 784;
                *reinterpret_cast<float2*>(Cm + (size_t)row * D_STATE + n)       = make_float2(v0, v1);
                *reinterpret_cast<float2*>(Cm + (size_t)(row + 8) * D_STATE + n) = make_float2(v2, v3);
            }
        }
    }
}

// ---------------- fp32 -> bf16 bulk convert ----------------------------------
__global__ void cvt_f32_bf16(const float* __restrict__ in, __nv_bfloat16* __restrict__ out, int n4)
{
    int idx = blockIdx.x * blockDim.x + threadIdx.x;
    if (idx >= n4) return;
    float4 v = reinterpret_cast<const float4*>(in)[idx];
    __nv_bfloat162 lo = { f2bf(v.x), f2bf(v.y) };
    __nv_bfloat162 hi = { f2bf(v.z), f2bf(v.w) };
    uint2 u = { *reinterpret_cast<uint32_t*>(&lo), *reinterpret_cast<uint32_t*>(&hi) };
    reinterpret_cast<uint2*>(out)[idx] = u;
}

// ---------------- build concatenated weight (bf16) ---------------------------
// rows 0..767 = W_dt; 768..783 = W_B; 784..799 = W_C; 800..895 = 0
__global__ void build_wcat(const float* __restrict__ W_dt, const float* __restrict__ W_B,
                           const float* __restrict__ W_C, __nv_bfloat16* __restrict__ out)
{
    int idx = blockIdx.x * blockDim.x + threadIdx.x;   // over NCAT*768/4
    if (idx >= NCAT * D_MODEL / 4) return;
    int r  = idx / (D_MODEL / 4);
    int c4 = (idx % (D_MODEL / 4)) * 4;
    float4 v = make_float4(0.f, 0.f, 0.f, 0.f);
    if (r < 768)      v = *reinterpret_cast<const float4*>(W_dt + (size_t)r * D_MODEL + c4);
    else if (r < 784) v = *reinterpret_cast<const float4*>(W_B + (size_t)(r - 768) * D_MODEL + c4);
    else if (r < 800) v = *reinterpret_cast<const float4*>(W_C + (size_t)(r - 784) * D_MODEL + c4);
    __nv_bfloat162 lo = { f2bf(v.x), f2bf(v.y) };
    __nv_bfloat162 hi = { f2bf(v.z), f2bf(v.w) };
    uint2 u = { *reinterpret_cast<uint32_t*>(&lo), *reinterpret_cast<uint32_t*>(&hi) };
    reinterpret_cast<uint2*>(out)[idx] = u;
}

// ---------------- depthwise causal conv (K=4) + bias + SiLU, bf16 in/out -----
__global__ void conv_silu_bf16(const __nv_bfloat16* __restrict__ xin,
                               const float* __restrict__ cw,
                               const float* __restrict__ cb,
                               __nv_bfloat16* __restrict__ out)
{
    int idx = blockIdx.x * blockDim.x + threadIdx.x;   // pair index
    if (idx >= M_ROWS * D_MODEL / 2) return;
    int d2 = idx % (D_MODEL / 2);
    int t  = (idx / (D_MODEL / 2)) % T_SEQ;
    int d  = d2 * 2;

    float a0 = cb[d], a1 = cb[d + 1];
    #pragma unroll
    for (int k = 0; k < D_CONV; k++) {
        int rel = k - (D_CONV - 1);
        if (t + rel >= 0) {
            __nv_bfloat162 xv = reinterpret_cast<const __nv_bfloat162*>(xin)[idx + rel * (D_MODEL / 2)];
            float f0 = __bfloat162float(xv.x), f1 = __bfloat162float(xv.y);
            a0 = fmaf(f0, cw[d * D_CONV + k], a0);
            a1 = fmaf(f1, cw[(d + 1) * D_CONV + k], a1);
        }
    }
    float s0 = a0 / (1.f + __expf(-a0));
    float s1 = a1 / (1.f + __expf(-a1));
    __nv_bfloat162 o = { f2bf(s0), f2bf(s1) };
    reinterpret_cast<__nv_bfloat162*>(out)[idx] = o;
}

// ---------------- scan helpers ------------------------------------------------
__device__ __forceinline__ void load_A_and_mode(const float* __restrict__ A_log,
                                                int d, float* A, bool& fast)
{
    #pragma unroll
    for (int n = 0; n < D_STATE; n++) A[n] = -__expf(A_log[d * D_STATE + n]);
    fast = true;
    #pragma unroll
    for (int n = 1; n < D_STATE; n++)
        fast = fast && (fabsf(A[n] - (float)(n + 1) * A[0]) <= 1e-4f * fabsf(A[n]));
}

// log-depth powers: pw[n] = p^(n+1)
__device__ __forceinline__ void powers16(float p1, float* pw)
{
    float p2 = p1 * p1, p4 = p2 * p2, p8 = p4 * p4;
    pw[0] = p1;        pw[1] = p2;        pw[2] = p2 * p1;   pw[3] = p4;
    pw[4] = p4 * p1;   pw[5] = p4 * p2;   pw[6] = p4 * pw[2]; pw[7] = p8;
    pw[8] = p8 * p1;   pw[9] = p8 * p2;   pw[10] = p8 * pw[2]; pw[11] = p8 * p4;
    pw[12] = p8 * pw[4]; pw[13] = p8 * pw[5]; pw[14] = p8 * pw[6]; pw[15] = p8 * p8;
}

// pass 1: per-chunk local scan from h=0; emit end-state and cumulative decay
__global__ __launch_bounds__(256)
void scan_pass1(const float* __restrict__ dt, const float* __restrict__ Bm,
                const float* __restrict__ x,  const float* __restrict__ A_log,
                float* __restrict__ hend, float* __restrict__ Pp)
{
    __shared__ float sB[TCH * D_STATE];
    int d  = blockIdx.x * blockDim.x + threadIdx.x;
    int ch = blockIdx.y;
    int b  = blockIdx.z;
    int t0 = ch * TCH;

    {
        const float4* src = reinterpret_cast<const float4*>(Bm + ((size_t)(b * T_SEQ + t0)) * D_STATE);
        float4* dst = reinterpret_cast<float4*>(sB);
        for (int i = threadIdx.x; i < TCH * D_STATE / 4; i += blockDim.x) dst[i] = src[i];
    }
    __syncthreads();

    float A[D_STATE]; bool fast;
    load_A_and_mode(A_log, d, A, fast);

    float h[D_STATE];
    #pragma unroll
    for (int n = 0; n < D_STATE; n++) h[n] = 0.f;

    const float* dtp = dt + ((size_t)(b * T_SEQ + t0)) * D_MODEL + d;
    const float* xp  = x  + ((size_t)(b * T_SEQ + t0)) * D_MODEL + d;
    size_t base = ((size_t)(b * NCH + ch) * D_STATE) * D_MODEL + d;

    if (fast) {
        float S = 0.f;
        for (int t = 0; t < TCH; t++) {
            float dtv = dtp[(size_t)t * D_MODEL];
            float xv  = xp [(size_t)t * D_MODEL];
            float u   = xv * dtv;
            S += dtv;
            float pw[16];
            powers16(__expf(A[0] * dtv), pw);
            const float* Bt = sB + t * D_STATE;
            #pragma unroll
            for (int n = 0; n < D_STATE; n++)
                h[n] = fmaf(h[n], pw[n], u * Bt[n]);
        }
        float pw[16];
        powers16(__expf(A[0] * S), pw);
        #pragma unroll
        for (int n = 0; n < D_STATE; n++) {
            hend[base + (size_t)n * D_MODEL] = h[n];
            Pp  [base + (size_t)n * D_MODEL] = pw[n];
        }
    } else {
        float P[D_STATE];
        #pragma unroll
        for (int n = 0; n < D_STATE; n++) P[n] = 1.f;
        for (int t = 0; t < TCH; t++) {
            float dtv = dtp[(size_t)t * D_MODEL];
            float xv  = xp [(size_t)t * D_MODEL];
            float u   = xv * dtv;
            const float* Bt = sB + t * D_STATE;
            #pragma unroll
            for (int n = 0; n < D_STATE; n++) {
                float pw = __expf(A[n] * dtv);
                h[n] = fmaf(h[n], pw, u * Bt[n]);
                P[n] *= pw;
            }
        }
        #pragma unroll
        for (int n = 0; n < D_STATE; n++) {
            hend[base + (size_t)n * D_MODEL] = h[n];
            Pp  [base + (size_t)n * D_MODEL] = P[n];
        }
    }
}

// pass 2: sequential combine over chunks -> chunk-entry states
__global__ void scan_combine(const float* __restrict__ hend, const float* __restrict__ Pp,
                             float* __restrict__ sin_)
{
    int idx = blockIdx.x * blockDim.x + threadIdx.x;
    if (idx >= B_SZ * D_STATE * D_MODEL) return;
    int d = idx % D_MODEL;
    int n = (idx / D_MODEL) % D_STATE;
    int b = idx / (D_MODEL * D_STATE);

    float s = 0.f;
    for (int ch = 0; ch < NCH; ch++) {
        size_t off = ((size_t)(b * NCH + ch) * D_STATE + n) * D_MODEL + d;
        sin_[off] = s;
        s = fmaf(Pp[off], s, hend[off]);
    }
}

// pass 3: replay chunks with correct entry state; emit y + residual
__global__ __launch_bounds__(256)
void scan_pass3(const float* __restrict__ dt, const float* __restrict__ Bm,
                const float* __restrict__ Cm, const float* __restrict__ x,
                const float* __restrict__ A_log, const float* __restrict__ Dp,
                const float* __restrict__ sin_, float* __restrict__ y)
{
    __shared__ float sB[TCH * D_STATE];
    __shared__ float sC[TCH * D_STATE];
    int d  = blockIdx.x * blockDim.x + threadIdx.x;
    int ch = blockIdx.y;
    int b  = blockIdx.z;
    int t0 = ch * TCH;

    {
        const float4* srcB = reinterpret_cast<const float4*>(Bm + ((size_t)(b * T_SEQ + t0)) * D_STATE);
        const float4* srcC = reinterpret_cast<const float4*>(Cm + ((size_t)(b * T_SEQ + t0)) * D_STATE);
        float4* dB = reinterpret_cast<float4*>(sB);
        float4* dC = reinterpret_cast<float4*>(sC);
        for (int i = threadIdx.x; i < TCH * D_STATE / 4; i += blockDim.x) { dB[i] = srcB[i]; dC[i] = srcC[i]; }
    }
    __syncthreads();

    float A[D_STATE]; bool fast;
    load_A_and_mode(A_log, d, A, fast);

    float h[D_STATE];
    size_t base = ((size_t)(b * NCH + ch) * D_STATE) * D_MODEL + d;
    #pragma unroll
    for (int n = 0; n < D_STATE; n++) h[n] = sin_[base + (size_t)n * D_MODEL];

    float dpar = Dp[d];
    const float* dtp = dt + ((size_t)(b * T_SEQ + t0)) * D_MODEL + d;
    const float* xp  = x  + ((size_t)(b * T_SEQ + t0)) * D_MODEL + d;
    float* yp        = y  + ((size_t)(b * T_SEQ + t0)) * D_MODEL + d;

    if (fast) {
        for (int t = 0; t < TCH; t++) {
            float dtv = dtp[(size_t)t * D_MODEL];
            float xv  = xp [(size_t)t * D_MODEL];
            float u   = xv * dtv;
            float pw[16];
            powers16(__expf(A[0] * dtv), pw);
            const float* Bt = sB + t * D_STATE;
            const float* Ct = sC + t * D_STATE;
            float acc = 0.f;
            #pragma unroll
            for (int n = 0; n < D_STATE; n++) {
                h[n] = fmaf(h[n], pw[n], u * Bt[n]);
                acc  = fmaf(h[n], Ct[n], acc);
            }
            yp[(size_t)t * D_MODEL] = fmaf(xv, dpar, acc);
        }
    } else {
        for (int t = 0; t < TCH; t++) {
            float dtv = dtp[(size_t)t * D_MODEL];
            float xv  = xp [(size_t)t * D_MODEL];
            float u   = xv * dtv;
            const float* Bt = sB + t * D_STATE;
            const float* Ct = sC + t * D_STATE;
            float acc = 0.f;
            #pragma unroll
            for (int n = 0; n < D_STATE; n++) {
                float pw = __expf(A[n] * dtv);
                h[n] = fmaf(h[n], pw, u * Bt[n]);
                acc  = fmaf(h[n], Ct[n], acc);
            }
            yp[(size_t)t * D_MODEL] = fmaf(xv, dpar, acc);
        }
    }
}

// ---------------- launch ------------------------------------------------------
extern "C" void kernel_launch(void* const* d_in, const int* in_sizes, int n_in,
                              void* d_out, int out_size)
{
    const float* x      = (const float*)d_in[0];
    const float* W_in   = (const float*)d_in[1];
    const float* conv_w = (const float*)d_in[2];
    const float* conv_b = (const float*)d_in[3];
    const float* W_dt   = (const float*)d_in[4];
    const float* b_dt   = (const float*)d_in[5];
    const float* A_log  = (const float*)d_in[6];
    const float* D_par  = (const float*)d_in[7];
    const float* W_B    = (const float*)d_in[8];
    const float* W_C    = (const float*)d_in[9];
    float* y = (float*)d_out;

    __nv_bfloat16 *xbf, *xssm_bf, *xconv_bf, *win_bf, *wcat_bf;
    float *dtb, *Bm, *Cm, *hend, *Pp, *sin_;
    cudaGetSymbolAddress((void**)&xbf,      g_xbf);
    cudaGetSymbolAddress((void**)&xssm_bf,  g_xssm_bf);
    cudaGetSymbolAddress((void**)&xconv_bf, g_xconv_bf);
    cudaGetSymbolAddress((void**)&win_bf,   g_Win_bf);
    cudaGetSymbolAddress((void**)&wcat_bf,  g_Wcat_bf);
    cudaGetSymbolAddress((void**)&dtb,   g_dt);
    cudaGetSymbolAddress((void**)&Bm,    g_Bm);
    cudaGetSymbolAddress((void**)&Cm,    g_Cm);
    cudaGetSymbolAddress((void**)&hend,  g_hend);
    cudaGetSymbolAddress((void**)&Pp,    g_Pp);
    cudaGetSymbolAddress((void**)&sin_,  g_sin);

    // 0) precision prep: x -> bf16; W_in[:768] -> bf16; [W_dt; W_B; W_C; 0] -> bf16
    int n4x = M_ROWS * D_MODEL / 4;
    cvt_f32_bf16<<<(n4x + 255) / 256, 256>>>(x, xbf, n4x);
    int n4w = D_MODEL * D_MODEL / 4;
    cvt_f32_bf16<<<(n4w + 255) / 256, 256>>>(W_in, win_bf, n4w);
    int n4c = NCAT * D_MODEL / 4;
    build_wcat<<<(n4c + 255) / 256, 256>>>(W_dt, W_B, W_C, wcat_bf);

    // 1) x_ssm = x @ W_in[:768].T  (z half is dead code); bf16 out
    dim3 g1(D_MODEL / 128, M_ROWS / 128);
    gemm_bf16<<<g1, 256>>>(xbf, win_bf, nullptr, xssm_bf, nullptr, nullptr, nullptr, 0);

    // 2) depthwise causal conv + bias + SiLU (bf16 -> bf16)
    int pairs = M_ROWS * D_MODEL / 2;
    conv_silu_bf16<<<(pairs + 255) / 256, 256>>>(xssm_bf, conv_w, conv_b, xconv_bf);

    // 3) fused: dt = softplus(xconv @ W_dt.T + b_dt); Bm = xconv @ W_B.T; Cm = xconv @ W_C.T
    dim3 g2(NCAT / 128, M_ROWS / 128);
    gemm_bf16<<<g2, 256>>>(xconv_bf, wcat_bf, b_dt, nullptr, dtb, Bm, Cm, 1);

    // 4-6) chunked associative scan
    dim3 scan_grid(D_MODEL / 256, NCH, B_SZ);
    scan_pass1<<<scan_grid, 256>>>(dtb, Bm, x, A_log, hend, Pp);
    scan_combine<<<(B_SZ * D_STATE * D_MODEL + 255) / 256, 256>>>(hend, Pp, sin_);
    scan_pass3<<<scan_grid, 256>>>(dtb, Bm, Cm, x, A_log, D_par, sin_, y);
}

// round 5
// speedup vs baseline: 5.4216x; 1.3298x over previous
#include <cuda_runtime.h>
#include <cuda_bf16.h>
#include <cstdint>

// Problem constants
#define B_SZ 8
#define T_SEQ 2048
#define D_MODEL 768
#define D_STATE 16
#define D_CONV 4
#define M_ROWS (B_SZ * T_SEQ)          // 16384
#define NCH 16                          // scan chunks
#define TCH (T_SEQ / NCH)               // 128 steps per chunk
#define NCAT 896                        // padded fused-GEMM2 N (768 dt + 16 B + 16 C + 96 pad)

// ---------------- scratch (__device__ globals; no runtime alloc) -------------
__device__ __nv_bfloat16 g_xbf     [M_ROWS * D_MODEL];
__device__ __nv_bfloat16 g_xssm_bf [M_ROWS * D_MODEL];
__device__ __nv_bfloat16 g_xconv_bf[M_ROWS * D_MODEL];
__device__ __nv_bfloat16 g_Win_bf  [D_MODEL * D_MODEL];
__device__ __nv_bfloat16 g_Wcat_bf [NCAT * D_MODEL];
__device__ float g_dt   [M_ROWS * D_MODEL];
__device__ float g_Bm   [M_ROWS * D_STATE];
__device__ float g_Cm   [M_ROWS * D_STATE];
__device__ float g_hend [B_SZ * NCH * D_STATE * D_MODEL];
__device__ float g_Pp   [B_SZ * NCH * D_STATE * D_MODEL];
__device__ float g_sin  [B_SZ * NCH * D_STATE * D_MODEL];

// ============================ PTX helpers =====================================
__device__ __forceinline__ uint32_t smem_u32(const void* p) {
    uint32_t a;
    asm("{ .reg .u64 t; cvta.to.shared.u64 t, %1; cvt.u32.u64 %0, t; }" : "=r"(a) : "l"(p));
    return a;
}
__device__ __forceinline__ void ldsm_x4(uint32_t addr, uint32_t& r0, uint32_t& r1,
                                        uint32_t& r2, uint32_t& r3) {
    asm volatile("ldmatrix.sync.aligned.m8n8.x4.shared.b16 {%0,%1,%2,%3}, [%4];"
                 : "=r"(r0), "=r"(r1), "=r"(r2), "=r"(r3) : "r"(addr));
}
__device__ __forceinline__ void mma_bf16(float* c,
                                         uint32_t a0, uint32_t a1, uint32_t a2, uint32_t a3,
                                         uint32_t b0, uint32_t b1) {
    asm volatile("mma.sync.aligned.m16n8k16.row.col.f32.bf16.bf16.f32 "
                 "{%0,%1,%2,%3}, {%4,%5,%6,%7}, {%8,%9}, {%0,%1,%2,%3};"
                 : "+f"(c[0]), "+f"(c[1]), "+f"(c[2]), "+f"(c[3])
                 : "r"(a0), "r"(a1), "r"(a2), "r"(a3), "r"(b0), "r"(b1));
}
__device__ __forceinline__ __nv_bfloat16 f2bf(float x) { return __float2bfloat16_rn(x); }

#define CP16(dst, src) \
    asm volatile("cp.async.cg.shared.global [%0], [%1], 16;" :: "r"(dst), "l"(src) : "memory")
#define CP_COMMIT()  asm volatile("cp.async.commit_group;" ::: "memory")
#define CP_WAIT1()   asm volatile("cp.async.wait_group 1;" ::: "memory")

// ===================== bf16 mma.sync GEMM =====================================
// C[M, N] = A[M, 768](bf16) * W[N, 768](bf16)^T, fp32 accumulate.
// tile 128x128, BK=32, 3-stage cp.async pipeline (dynamic smem). 8 warps, 64x32 each.
// mode 0: write bf16 to outBF (no act).
// mode 1: fused epilogue: cols <768 -> softplus(v + bias) into outDT (fp32);
//         cols 768..783 -> Bm; 784..799 -> Cm; >=800 discard.
#define GK 768
#define CHKB 32
#define NKB (GK / CHKB)                 // 24
#define SRB 40                          // 32 + 8 pad bf16 (80B row; LDSM conflict-free)
#define ROWB (SRB * 2)                  // 80 bytes per smem row
#define MATB (128 * ROWB)               // 10240 bytes per matrix per stage
#define STGB (2 * MATB)                 // 20480 bytes per stage (A + W)
#define GEMM_SMEM (3 * STGB)            // 61440

__global__ __launch_bounds__(256, 2)
void gemm_bf16(const __nv_bfloat16* __restrict__ A, const __nv_bfloat16* __restrict__ W,
               const float* __restrict__ bias, __nv_bfloat16* __restrict__ outBF,
               float* __restrict__ outDT, float* __restrict__ Bm, float* __restrict__ Cm,
               int mode)
{
    extern __shared__ __align__(16) char smem_raw[];
    const uint32_t sbase = smem_u32(smem_raw);

    const int tid  = threadIdx.x;
    const int wid  = tid >> 5;
    const int lane = tid & 31;
    const int bn   = blockIdx.x * 128;
    const int bm   = blockIdx.y * 128;
    const int wm   = (wid & 1) * 64;
    const int wn   = (wid >> 1) * 32;

    float acc[4][4][4];
    #pragma unroll
    for (int i = 0; i < 4; i++)
        #pragma unroll
        for (int j = 0; j < 4; j++)
            #pragma unroll
            for (int c = 0; c < 4; c++) acc[i][j][c] = 0.f;

    // cp.async pattern: per chunk per matrix 128 rows x 64B = 512 x 16B; 2/thread/matrix
    const int r0 = tid >> 2;              // 0..63
    const int c8 = (tid & 3) * 8;         // bf16 elem offset 0,8,16,24
    const __nv_bfloat16* Aptr = A + (size_t)(bm + r0) * GK + c8;
    const __nv_bfloat16* Wptr = W + (size_t)(bn + r0) * GK + c8;
    const size_t gstep = (size_t)64 * GK;

    const uint32_t dA0 = sbase + (uint32_t)(r0 * ROWB + c8 * 2);
    const uint32_t dW0 = dA0 + MATB;

    auto issue = [&](int k) {
        uint32_t off = (uint32_t)(k % 3) * STGB;
        const __nv_bfloat16* a0 = Aptr + (size_t)k * CHKB;
        const __nv_bfloat16* w0 = Wptr + (size_t)k * CHKB;
        CP16(dA0 + off,                 a0);
        CP16(dA0 + off + 64u * ROWB,    a0 + gstep);
        CP16(dW0 + off,                 w0);
        CP16(dW0 + off + 64u * ROWB,    w0 + gstep);
        CP_COMMIT();
    };

    // ldmatrix lane addressing (validated round 4)
    const int arow = lane & 15;                       // A: rows m0..15
    const int ak   = (lane >> 4) * 8;                 // A: k half
    const int brow = ((lane >> 4) * 8) + (lane & 7);  // B: n row within 16
    const int bk   = ((lane >> 3) & 1) * 8;           // B: k half

    const uint32_t aAddr0 = sbase + (uint32_t)((wm + arow) * ROWB + ak * 2);
    const uint32_t bAddr0 = sbase + MATB + (uint32_t)((wn + brow) * ROWB + bk * 2);

    issue(0);
    issue(1);

    for (int k = 0; k < NKB; k++) {
        CP_WAIT1();
        __syncthreads();
        if (k + 2 < NKB) issue(k + 2);

        const uint32_t off = (uint32_t)(k % 3) * STGB;
        #pragma unroll
        for (int ks = 0; ks < 2; ks++) {
            const uint32_t koff = off + (uint32_t)(ks * 32);   // 16 bf16 = 32 bytes
            uint32_t bf[4][2];
            ldsm_x4(bAddr0 + koff,               bf[0][0], bf[0][1], bf[1][0], bf[1][1]);
            ldsm_x4(bAddr0 + koff + 16u * ROWB,  bf[2][0], bf[2][1], bf[3][0], bf[3][1]);
            #pragma unroll
            for (int mf = 0; mf < 4; mf++) {
                uint32_t a0, a1, a2, a3;
                ldsm_x4(aAddr0 + koff + (uint32_t)(mf * 16 * ROWB), a0, a1, a2, a3);
                #pragma unroll
                for (int nf = 0; nf < 4; nf++)
                    mma_bf16(acc[mf][nf], a0, a1, a2, a3, bf[nf][0], bf[nf][1]);
            }
        }
    }

    // epilogue: c0/c1 = (row, col/col+1); c2/c3 = row+8
    const int erow = lane >> 2;
    const int ecol = (lane & 3) * 2;
    #pragma unroll
    for (int mf = 0; mf < 4; mf++) {
        int row = bm + wm + mf * 16 + erow;
        #pragma unroll
        for (int nf = 0; nf < 4; nf++) {
            int col = bn + wn + nf * 8 + ecol;
            float v0 = acc[mf][nf][0], v1 = acc[mf][nf][1];
            float v2 = acc[mf][nf][2], v3 = acc[mf][nf][3];
            if (mode == 0) {
                __nv_bfloat162 p0 = { f2bf(v0), f2bf(v1) };
                __nv_bfloat162 p1 = { f2bf(v2), f2bf(v3) };
                *reinterpret_cast<__nv_bfloat162*>(outBF + (size_t)row * D_MODEL + col)       = p0;
                *reinterpret_cast<__nv_bfloat162*>(outBF + (size_t)(row + 8) * D_MODEL + col) = p1;
            } else if (col < 768) {
                float b0 = bias[col], b1 = bias[col + 1];
                v0 += b0; v1 += b1; v2 += b0; v3 += b1;
                v0 = (v0 > 20.f) ? v0 : log1pf(__expf(v0));
                v1 = (v1 > 20.f) ? v1 : log1pf(__expf(v1));
                v2 = (v2 > 20.f) ? v2 : log1pf(__expf(v2));
                v3 = (v3 > 20.f) ? v3 : log1pf(__expf(v3));
                *reinterpret_cast<float2*>(outDT + (size_t)row * D_MODEL + col)       = make_float2(v0, v1);
                *reinterpret_cast<float2*>(outDT + (size_t)(row + 8) * D_MODEL + col) = make_float2(v2, v3);
            } else if (col < 784) {
                int n = col - 768;
                *reinterpret_cast<float2*>(Bm + (size_t)row * D_STATE + n)       = make_float2(v0, v1);
                *reinterpret_cast<float2*>(Bm + (size_t)(row + 8) * D_STATE + n) = make_float2(v2, v3);
            } else if (col < 800) {
                int n = col - 784;
                *reinterpret_cast<float2*>(Cm + (size_t)row * D_STATE + n)       = make_float2(v0, v1);
                *reinterpret_cast<float2*>(Cm + (size_t)(row + 8) * D_STATE + n) = make_float2(v2, v3);
            }
        }
    }
}

// ---------------- fp32 -> bf16 bulk convert ----------------------------------
__global__ void cvt_f32_bf16(const float* __restrict__ in, __nv_bfloat16* __restrict__ out, int n4)
{
    int idx = blockIdx.x * blockDim.x + threadIdx.x;
    if (idx >= n4) return;
    float4 v = reinterpret_cast<const float4*>(in)[idx];
    __nv_bfloat162 lo = { f2bf(v.x), f2bf(v.y) };
    __nv_bfloat162 hi = { f2bf(v.z), f2bf(v.w) };
    uint2 u = { *reinterpret_cast<uint32_t*>(&lo), *reinterpret_cast<uint32_t*>(&hi) };
    reinterpret_cast<uint2*>(out)[idx] = u;
}

// ---------------- build concatenated weight (bf16) ---------------------------
__global__ void build_wcat(const float* __restrict__ W_dt, const float* __restrict__ W_B,
                           const float* __restrict__ W_C, __nv_bfloat16* __restrict__ out)
{
    int idx = blockIdx.x * blockDim.x + threadIdx.x;
    if (idx >= NCAT * D_MODEL / 4) return;
    int r  = idx / (D_MODEL / 4);
    int c4 = (idx % (D_MODEL / 4)) * 4;
    float4 v = make_float4(0.f, 0.f, 0.f, 0.f);
    if (r < 768)      v = *reinterpret_cast<const float4*>(W_dt + (size_t)r * D_MODEL + c4);
    else if (r < 784) v = *reinterpret_cast<const float4*>(W_B + (size_t)(r - 768) * D_MODEL + c4);
    else if (r < 800) v = *reinterpret_cast<const float4*>(W_C + (size_t)(r - 784) * D_MODEL + c4);
    __nv_bfloat162 lo = { f2bf(v.x), f2bf(v.y) };
    __nv_bfloat162 hi = { f2bf(v.z), f2bf(v.w) };
    uint2 u = { *reinterpret_cast<uint32_t*>(&lo), *reinterpret_cast<uint32_t*>(&hi) };
    reinterpret_cast<uint2*>(out)[idx] = u;
}

// ---------------- depthwise causal conv (K=4) + bias + SiLU, bf16 in/out -----
__global__ void conv_silu_bf16(const __nv_bfloat16* __restrict__ xin,
                               const float* __restrict__ cw,
                               const float* __restrict__ cb,
                               __nv_bfloat16* __restrict__ out)
{
    int idx = blockIdx.x * blockDim.x + threadIdx.x;   // pair index
    if (idx >= M_ROWS * D_MODEL / 2) return;
    int d2 = idx % (D_MODEL / 2);
    int t  = (idx / (D_MODEL / 2)) % T_SEQ;
    int d  = d2 * 2;

    float a0 = cb[d], a1 = cb[d + 1];
    #pragma unroll
    for (int k = 0; k < D_CONV; k++) {
        int rel = k - (D_CONV - 1);
        if (t + rel >= 0) {
            __nv_bfloat162 xv = reinterpret_cast<const __nv_bfloat162*>(xin)[idx + rel * (D_MODEL / 2)];
            float f0 = __bfloat162float(xv.x), f1 = __bfloat162float(xv.y);
            a0 = fmaf(f0, cw[d * D_CONV + k], a0);
            a1 = fmaf(f1, cw[(d + 1) * D_CONV + k], a1);
        }
    }
    float s0 = a0 / (1.f + __expf(-a0));
    float s1 = a1 / (1.f + __expf(-a1));
    __nv_bfloat162 o = { f2bf(s0), f2bf(s1) };
    reinterpret_cast<__nv_bfloat162*>(out)[idx] = o;
}

// ---------------- scan helpers ------------------------------------------------
__device__ __forceinline__ void load_A_and_mode(const float* __restrict__ A_log,
                                                int d, float* A, bool& fast)
{
    #pragma unroll
    for (int n = 0; n < D_STATE; n++) A[n] = -__expf(A_log[d * D_STATE + n]);
    fast = true;
    #pragma unroll
    for (int n = 1; n < D_STATE; n++)
        fast = fast && (fabsf(A[n] - (float)(n + 1) * A[0]) <= 1e-4f * fabsf(A[n]));
}

// log-depth powers: pw[n] = p^(n+1)
__device__ __forceinline__ void powers16(float p1, float* pw)
{
    float p2 = p1 * p1, p4 = p2 * p2, p8 = p4 * p4;
    pw[0] = p1;        pw[1] = p2;        pw[2] = p2 * p1;   pw[3] = p4;
    pw[4] = p4 * p1;   pw[5] = p4 * p2;   pw[6] = p4 * pw[2]; pw[7] = p8;
    pw[8] = p8 * p1;   pw[9] = p8 * p2;   pw[10] = p8 * pw[2]; pw[11] = p8 * p4;
    pw[12] = p8 * pw[4]; pw[13] = p8 * pw[5]; pw[14] = p8 * pw[6]; pw[15] = p8 * p8;
}

// pass 1: per-chunk local scan from h=0; emit end-state and cumulative decay
__global__ __launch_bounds__(256)
void scan_pass1(const float* __restrict__ dt, const float* __restrict__ Bm,
                const float* __restrict__ x,  const float* __restrict__ A_log,
                float* __restrict__ hend, float* __restrict__ Pp)
{
    __shared__ float sB[TCH * D_STATE];
    int d  = blockIdx.x * blockDim.x + threadIdx.x;
    int ch = blockIdx.y;
    int b  = blockIdx.z;
    int t0 = ch * TCH;

    {
        const float4* src = reinterpret_cast<const float4*>(Bm + ((size_t)(b * T_SEQ + t0)) * D_STATE);
        float4* dst = reinterpret_cast<float4*>(sB);
        for (int i = threadIdx.x; i < TCH * D_STATE / 4; i += blockDim.x) dst[i] = src[i];
    }
    __syncthreads();

    float A[D_STATE]; bool fast;
    load_A_and_mode(A_log, d, A, fast);

    float h[D_STATE];
    #pragma unroll
    for (int n = 0; n < D_STATE; n++) h[n] = 0.f;

    const float* dtp = dt + ((size_t)(b * T_SEQ + t0)) * D_MODEL + d;
    const float* xp  = x  + ((size_t)(b * T_SEQ + t0)) * D_MODEL + d;
    size_t base = ((size_t)(b * NCH + ch) * D_STATE) * D_MODEL + d;

    if (fast) {
        float S = 0.f;
        for (int t = 0; t < TCH; t += 4) {
            float dtv[4], xv[4];
            #pragma unroll
            for (int j = 0; j < 4; j++) {
                dtv[j] = dtp[(size_t)(t + j) * D_MODEL];
                xv[j]  = xp [(size_t)(t + j) * D_MODEL];
            }
            #pragma unroll
            for (int j = 0; j < 4; j++) {
                float u = xv[j] * dtv[j];
                S += dtv[j];
                float pw[16];
                powers16(__expf(A[0] * dtv[j]), pw);
                const float* Bt = sB + (t + j) * D_STATE;
                #pragma unroll
                for (int n = 0; n < D_STATE; n++)
                    h[n] = fmaf(h[n], pw[n], u * Bt[n]);
            }
        }
        float pw[16];
        powers16(__expf(A[0] * S), pw);
        #pragma unroll
        for (int n = 0; n < D_STATE; n++) {
            hend[base + (size_t)n * D_MODEL] = h[n];
            Pp  [base + (size_t)n * D_MODEL] = pw[n];
        }
    } else {
        float P[D_STATE];
        #pragma unroll
        for (int n = 0; n < D_STATE; n++) P[n] = 1.f;
        for (int t = 0; t < TCH; t++) {
            float dtv = dtp[(size_t)t * D_MODEL];
            float xv  = xp [(size_t)t * D_MODEL];
            float u   = xv * dtv;
            const float* Bt = sB + t * D_STATE;
            #pragma unroll
            for (int n = 0; n < D_STATE; n++) {
                float pw = __expf(A[n] * dtv);
                h[n] = fmaf(h[n], pw, u * Bt[n]);
                P[n] *= pw;
            }
        }
        #pragma unroll
        for (int n = 0; n < D_STATE; n++) {
            hend[base + (size_t)n * D_MODEL] = h[n];
            Pp  [base + (size_t)n * D_MODEL] = P[n];
        }
    }
}

// pass 2: sequential combine over chunks -> chunk-entry states
__global__ void scan_combine(const float* __restrict__ hend, const float* __restrict__ Pp,
                             float* __restrict__ sin_)
{
    int idx = blockIdx.x * blockDim.x + threadIdx.x;
    if (idx >= B_SZ * D_STATE * D_MODEL) return;
    int d = idx % D_MODEL;
    int n = (idx / D_MODEL) % D_STATE;
    int b = idx / (D_MODEL * D_STATE);

    float s = 0.f;
    for (int ch = 0; ch < NCH; ch++) {
        size_t off = ((size_t)(b * NCH + ch) * D_STATE + n) * D_MODEL + d;
        sin_[off] = s;
        s = fmaf(Pp[off], s, hend[off]);
    }
}

// pass 3: replay chunks with correct entry state; emit y + residual
__global__ __launch_bounds__(256)
void scan_pass3(const float* __restrict__ dt, const float* __restrict__ Bm,
                const float* __restrict__ Cm, const float* __restrict__ x,
                const float* __restrict__ A_log, const float* __restrict__ Dp,
                const float* __restrict__ sin_, float* __restrict__ y)
{
    __shared__ float sB[TCH * D_STATE];
    __shared__ float sC[TCH * D_STATE];
    int d  = blockIdx.x * blockDim.x + threadIdx.x;
    int ch = blockIdx.y;
    int b  = blockIdx.z;
    int t0 = ch * TCH;

    {
        const float4* srcB = reinterpret_cast<const float4*>(Bm + ((size_t)(b * T_SEQ + t0)) * D_STATE);
        const float4* srcC = reinterpret_cast<const float4*>(Cm + ((size_t)(b * T_SEQ + t0)) * D_STATE);
        float4* dB = reinterpret_cast<float4*>(sB);
        float4* dC = reinterpret_cast<float4*>(sC);
        for (int i = threadIdx.x; i < TCH * D_STATE / 4; i += blockDim.x) { dB[i] = srcB[i]; dC[i] = srcC[i]; }
    }
    __syncthreads();

    float A[D_STATE]; bool fast;
    load_A_and_mode(A_log, d, A, fast);

    float h[D_STATE];
    size_t base = ((size_t)(b * NCH + ch) * D_STATE) * D_MODEL + d;
    #pragma unroll
    for (int n = 0; n < D_STATE; n++) h[n] = sin_[base + (size_t)n * D_MODEL];

    float dpar = Dp[d];
    const float* dtp = dt + ((size_t)(b * T_SEQ + t0)) * D_MODEL + d;
    const float* xp  = x  + ((size_t)(b * T_SEQ + t0)) * D_MODEL + d;
    float* yp        = y  + ((size_t)(b * T_SEQ + t0)) * D_MODEL + d;

    if (fast) {
        for (int t = 0; t < TCH; t += 4) {
            float dtv[4], xv[4];
            #pragma unroll
            for (int j = 0; j < 4; j++) {
                dtv[j] = dtp[(size_t)(t + j) * D_MODEL];
                xv[j]  = xp [(size_t)(t + j) * D_MODEL];
            }
            float yv[4];
            #pragma unroll
            for (int j = 0; j < 4; j++) {
                float u = xv[j] * dtv[j];
                float pw[16];
                powers16(__expf(A[0] * dtv[j]), pw);
                const float* Bt = sB + (t + j) * D_STATE;
                const float* Ct = sC + (t + j) * D_STATE;
                float acc = 0.f;
                #pragma unroll
                for (int n = 0; n < D_STATE; n++) {
                    h[n] = fmaf(h[n], pw[n], u * Bt[n]);
                    acc  = fmaf(h[n], Ct[n], acc);
                }
                yv[j] = fmaf(xv[j], dpar, acc);
            }
            #pragma unroll
            for (int j = 0; j < 4; j++)
                yp[(size_t)(t + j) * D_MODEL] = yv[j];
        }
    } else {
        for (int t = 0; t < TCH; t++) {
            float dtv = dtp[(size_t)t * D_MODEL];
            float xv  = xp [(size_t)t * D_MODEL];
            float u   = xv * dtv;
            const float* Bt = sB + t * D_STATE;
            const float* Ct = sC + t * D_STATE;
            float acc = 0.f;
            #pragma unroll
            for (int n = 0; n < D_STATE; n++) {
                float pw = __expf(A[n] * dtv);
                h[n] = fmaf(h[n], pw, u * Bt[n]);
                acc  = fmaf(h[n], Ct[n], acc);
            }
            yp[(size_t)t * D_MODEL] = fmaf(xv, dpar, acc);
        }
    }
}

// ---------------- launch ------------------------------------------------------
extern "C" void kernel_launch(void* const* d_in, const int* in_sizes, int n_in,
                              void* d_out, int out_size)
{
    const float* x      = (const float*)d_in[0];
    const float* W_in   = (const float*)d_in[1];
    const float* conv_w = (const float*)d_in[2];
    const float* conv_b = (const float*)d_in[3];
    const float* W_dt   = (const float*)d_in[4];
    const float* b_dt   = (const float*)d_in[5];
    const float* A_log  = (const float*)d_in[6];
    const float* D_par  = (const float*)d_in[7];
    const float* W_B    = (const float*)d_in[8];
    const float* W_C    = (const float*)d_in[9];
    float* y = (float*)d_out;

    __nv_bfloat16 *xbf, *xssm_bf, *xconv_bf, *win_bf, *wcat_bf;
    float *dtb, *Bm, *Cm, *hend, *Pp, *sin_;
    cudaGetSymbolAddress((void**)&xbf,      g_xbf);
    cudaGetSymbolAddress((void**)&xssm_bf,  g_xssm_bf);
    cudaGetSymbolAddress((void**)&xconv_bf, g_xconv_bf);
    cudaGetSymbolAddress((void**)&win_bf,   g_Win_bf);
    cudaGetSymbolAddress((void**)&wcat_bf,  g_Wcat_bf);
    cudaGetSymbolAddress((void**)&dtb,   g_dt);
    cudaGetSymbolAddress((void**)&Bm,    g_Bm);
    cudaGetSymbolAddress((void**)&Cm,    g_Cm);
    cudaGetSymbolAddress((void**)&hend,  g_hend);
    cudaGetSymbolAddress((void**)&Pp,    g_Pp);
    cudaGetSymbolAddress((void**)&sin_,  g_sin);

    cudaFuncSetAttribute(gemm_bf16, cudaFuncAttributeMaxDynamicSharedMemorySize, GEMM_SMEM);

    // 0) precision prep: x -> bf16; W_in[:768] -> bf16; [W_dt; W_B; W_C; 0] -> bf16
    int n4x = M_ROWS * D_MODEL / 4;
    cvt_f32_bf16<<<(n4x + 255) / 256, 256>>>(x, xbf, n4x);
    int n4w = D_MODEL * D_MODEL / 4;
    cvt_f32_bf16<<<(n4w + 255) / 256, 256>>>(W_in, win_bf, n4w);
    int n4c = NCAT * D_MODEL / 4;
    build_wcat<<<(n4c + 255) / 256, 256>>>(W_dt, W_B, W_C, wcat_bf);

    // 1) x_ssm = x @ W_in[:768].T  (z half is dead code); bf16 out
    dim3 g1(D_MODEL / 128, M_ROWS / 128);
    gemm_bf16<<<g1, 256, GEMM_SMEM>>>(xbf, win_bf, nullptr, xssm_bf, nullptr, nullptr, nullptr, 0);

    // 2) depthwise causal conv + bias + SiLU (bf16 -> bf16)
    int pairs = M_ROWS * D_MODEL / 2;
    conv_silu_bf16<<<(pairs + 255) / 256, 256>>>(xssm_bf, conv_w, conv_b, xconv_bf);

    // 3) fused: dt = softplus(xconv @ W_dt.T + b_dt); Bm = xconv @ W_B.T; Cm = xconv @ W_C.T
    dim3 g2(NCAT / 128, M_ROWS / 128);
    gemm_bf16<<<g2, 256, GEMM_SMEM>>>(xconv_bf, wcat_bf, b_dt, nullptr, dtb, Bm, Cm, 1);

    // 4-6) chunked associative scan
    dim3 scan_grid(D_MODEL / 256, NCH, B_SZ);
    scan_pass1<<<scan_grid, 256>>>(dtb, Bm, x, A_log, hend, Pp);
    scan_combine<<<(B_SZ * D_STATE * D_MODEL + 255) / 256, 256>>>(hend, Pp, sin_);
    scan_pass3<<<scan_grid, 256>>>(dtb, Bm, Cm, x, A_log, D_par, sin_, y);
}